// round 15
// baseline (speedup 1.0000x reference)
#include <cuda_runtime.h>
#include <cuda_bf16.h>

// Dilate (zero-insertion upsample) with stride (2,2):
//   in : (16, 64, 256, 256) fp32
//   out: (16, 64, 512, 512) fp32, out[b,c,2i,2j] = in[b,c,i,j], rest 0.
//
// MLP=8 probe (last untested point on the only productive axis; MLP 1->2->4
// gave 198.4 -> 194.6 -> 192.0 us ncu). Warp w handles output rows w and
// w + 262144: 262144 = 512*512, so both rows share h parity (branch stays
// warp-uniform) but sit in different images. Even warps: 8 front-batched
// 256B-coalesced loads + 8 warp-contiguous 512B stores. Odd warps: 8 zero
// stores. Everything else at the measured optimum (256 thr/block, __ldcs).
// Traffic: 268MB read + 1.074GB write = the exact floor.

#ifndef DIL_THREADS
#define DIL_THREADS 256
#endif

__global__ void __launch_bounds__(DIL_THREADS)
Dilate_35708358099161_kernel(const float2* __restrict__ in2,
                             float4* __restrict__ out4)
{
    unsigned int tid  = blockIdx.x * DIL_THREADS + threadIdx.x;
    unsigned int w    = tid >> 5;        // warp id, 0..262143
    unsigned int lane = tid & 31u;

    unsigned int row0 = w;               // first output row
    unsigned int row1 = w + 262144u;     // second row: same h parity, other half
    unsigned int h    = row0 & 511u;     // parity shared by both rows

    unsigned int v0 = (row0 << 7) + lane;  // float4 base, row 0
    unsigned int v1 = (row1 << 7) + lane;  // float4 base, row 1

    const float4 z = make_float4(0.f, 0.f, 0.f, 0.f);

    if (h & 1u) {
        out4[v0]      = z;  out4[v0 + 32] = z;
        out4[v0 + 64] = z;  out4[v0 + 96] = z;
        out4[v1]      = z;  out4[v1 + 32] = z;
        out4[v1 + 64] = z;  out4[v1 + 96] = z;
    } else {
        unsigned int hin = h >> 1;
        unsigned int bc0 = row0 >> 9;
        unsigned int bc1 = row1 >> 9;
        unsigned int b0  = (bc0 << 15) + (hin << 7) + lane;  // float2 units
        unsigned int b1  = (bc1 << 15) + (hin << 7) + lane;

        // eight independent 256B-coalesced loads, front-batched (MLP=8)
        float2 a0 = __ldcs(&in2[b0]);
        float2 a1 = __ldcs(&in2[b0 + 32]);
        float2 a2 = __ldcs(&in2[b0 + 64]);
        float2 a3 = __ldcs(&in2[b0 + 96]);
        float2 c0 = __ldcs(&in2[b1]);
        float2 c1 = __ldcs(&in2[b1 + 32]);
        float2 c2 = __ldcs(&in2[b1 + 64]);
        float2 c3 = __ldcs(&in2[b1 + 96]);

        out4[v0]      = make_float4(a0.x, 0.f, a0.y, 0.f);
        out4[v0 + 32] = make_float4(a1.x, 0.f, a1.y, 0.f);
        out4[v0 + 64] = make_float4(a2.x, 0.f, a2.y, 0.f);
        out4[v0 + 96] = make_float4(a3.x, 0.f, a3.y, 0.f);
        out4[v1]      = make_float4(c0.x, 0.f, c0.y, 0.f);
        out4[v1 + 32] = make_float4(c1.x, 0.f, c1.y, 0.f);
        out4[v1 + 64] = make_float4(c2.x, 0.f, c2.y, 0.f);
        out4[v1 + 96] = make_float4(c3.x, 0.f, c3.y, 0.f);
    }
}

extern "C" void kernel_launch(void* const* d_in, const int* in_sizes, int n_in,
                              void* d_out, int out_size)
{
    const float2* in2 = (const float2*)d_in[0];
    float4* out4 = (float4*)d_out;

    // 524,288 out rows, 2 per warp -> 262,144 warps -> 8,388,608 threads
    const unsigned int nthreads = (unsigned int)(out_size / 32);
    const unsigned int blocks = nthreads / DIL_THREADS;  // exact: 32,768

    Dilate_35708358099161_kernel<<<blocks, DIL_THREADS>>>(in2, out4);
}

// round 16
// speedup vs baseline: 1.0097x; 1.0097x over previous
#include <cuda_runtime.h>
#include <cuda_bf16.h>

// Dilate (zero-insertion upsample) with stride (2,2):
//   in : (16, 64, 256, 256) fp32
//   out: (16, 64, 512, 512) fp32, out[b,c,2i,2j] = in[b,c,i,j], rest 0.
//
// FINAL — measured optimum, exhaustively characterized over 15 rounds.
// 7 ncu runs of this structure: 193.3 +- 1.3 us, DRAM 83.7 +- 0.7%,
// ~6.65 TB/s = the chip's 4:1 W:R mixed-stream DRAM ceiling.
// Every axis probed in both directions, optimum interior on each:
//   - MLP/warp: 1/2/4/8 -> 198.4/194.6/192.0/194.8 us; 4 optimal
//   - block: 128/256/512 -> 82.5/84.4/75.8% DRAM; 256 optimal
//   - stores: must be warp-contiguous (strided -6%); width 128 vs 256-bit
//     identical; cache hint neutral
//   - warp-uniform parity branch kept (branch-free variant -1%)
// Structure: one 2KB output row per WARP; lane handles float4 offsets
// lane + {0,32,64,96} -> four warp-contiguous 512B stores; even rows
// front-batch four 256B-coalesced input loads.
// Traffic: 268MB read + 1.074GB write = the exact floor.

#ifndef DIL_THREADS
#define DIL_THREADS 256
#endif

__global__ void __launch_bounds__(DIL_THREADS)
Dilate_35708358099161_kernel(const float2* __restrict__ in2,
                             float4* __restrict__ out4)
{
    unsigned int tid  = blockIdx.x * DIL_THREADS + threadIdx.x;
    unsigned int row  = tid >> 5;        // global output row, one per warp
    unsigned int lane = tid & 31u;

    unsigned int h = row & 511u;         // out row within image
    unsigned int v = (row << 7) + lane;  // first float4 index for this lane

    const float4 z = make_float4(0.f, 0.f, 0.f, 0.f);

    if (h & 1u) {
        out4[v]      = z;
        out4[v + 32] = z;
        out4[v + 64] = z;
        out4[v + 96] = z;
    } else {
        unsigned int bc   = row >> 9;    // image index, 0..1023
        unsigned int hin  = h >> 1;      // input row, 0..255
        unsigned int base = (bc << 15) + (hin << 7) + lane;  // float2 units

        // four independent 256B-coalesced loads (full 1KB input row per warp)
        float2 a = __ldcs(&in2[base]);
        float2 b = __ldcs(&in2[base + 32]);
        float2 c = __ldcs(&in2[base + 64]);
        float2 d = __ldcs(&in2[base + 96]);

        out4[v]      = make_float4(a.x, 0.f, a.y, 0.f);
        out4[v + 32] = make_float4(b.x, 0.f, b.y, 0.f);
        out4[v + 64] = make_float4(c.x, 0.f, c.y, 0.f);
        out4[v + 96] = make_float4(d.x, 0.f, d.y, 0.f);
    }
}

extern "C" void kernel_launch(void* const* d_in, const int* in_sizes, int n_in,
                              void* d_out, int out_size)
{
    const float2* in2 = (const float2*)d_in[0];
    float4* out4 = (float4*)d_out;

    // out rows = out_size / 512 = 524,288; one warp per row
    const unsigned int nthreads = (unsigned int)(out_size / 16);
    const unsigned int blocks = nthreads / DIL_THREADS;  // exact: 65,536

    Dilate_35708358099161_kernel<<<blocks, DIL_THREADS>>>(in2, out4);
}